// round 13
// baseline (speedup 1.0000x reference)
#include <cuda_runtime.h>
#include <math.h>

#define N_   512
#define M_   2048
#define C_   256
#define KTOP 6

#define TMm 128
#define TNn 64
#define TK  16
#define MTILES  (M_ / TMm)                  // 16
#define NBLK    ((M_ / TMm) * (N_ / TNn))   // 128 blocks, all co-resident
#define ROWS_PB (N_ / NBLK)                 // 4 rows per block in phase 2

typedef unsigned long long ull;
typedef unsigned int u32;

// Scratch (static __device__ globals: allocation-free per harness rules)
__device__ ull   g_cand[N_][MTILES * KTOP];   // packed (ord(val)<<32 | ~col)
__device__ float g_rowco[N_];
__device__ int   g_bar1 = 0, g_bar2 = 0;
__device__ volatile int g_flag = 0;

// ---- packed f32x2 helpers (FFMA2: 2 FMA per instruction on sm_103a) -------
__device__ __forceinline__ ull pack2(float x) {
    ull r; asm("mov.b64 %0, {%1, %1};" : "=l"(r) : "f"(x)); return r;
}
__device__ __forceinline__ void fma2(ull& d, ull a, ull b) {
    asm("fma.rn.f32x2 %0, %1, %2, %0;" : "+l"(d) : "l"(a), "l"(b));
}
__device__ __forceinline__ void unpack2(ull v, float& lo, float& hi) {
    asm("mov.b64 {%0, %1}, %2;" : "=f"(lo), "=f"(hi) : "l"(v));
}
// ---- order-preserving float <-> u32 (monotone under unsigned compare) -----
__device__ __forceinline__ u32 ordf(float v) {
    u32 s = __float_as_uint(v);
    return s ^ (u32)(((int)s >> 31) | 0x80000000);
}
__device__ __forceinline__ float deordf(u32 o) {
    u32 s = (o & 0x80000000u) ? (o ^ 0x80000000u) : ~o;
    return __uint_as_float(s);
}

// ---------------------------------------------------------------------------
// Single fused kernel, 128 blocks x 256 threads (all co-resident: 128 <= 148
// SMs at 1 CTA/SM -> software grid barrier is deadlock-free).
//
// Phase 1 (GEMM + candidate epilogue):
//   anti[n,m] = Aq[m] - 2*dot(w'*micro[n], micro_all[m]),  w' = fc_w - 1/C
//   (per-row Bq[n] dropped: row-constant, invariant for top-k + exp weights)
//   Tile 128m x 64n x 256k, 256 thr (2 warps/SMSP), frag 4n x 8m, ull accs.
//   Epilogue: per-row top-6 of the 128-col tile as u64 keys
//   key = ord(val)<<32 | ~col : unsigned max == (val desc, col asc) — exact
//   lax.top_k order. Per-tile top-6 is sufficient for global top-6.
//
// Phase 2 (after grid barrier): each block merges 96 keys for its 4 rows,
//   builds exp weights over the 6 (full softmax denominator cancels),
//   writes output rows; last block reduces co_loss (fixed-order tree) and
//   resets barrier state for graph replays.
// ---------------------------------------------------------------------------
__global__ void __launch_bounds__(256)
fused(const float* __restrict__ micro,
      const float* __restrict__ micro_all,
      const float* __restrict__ label,
      const float* __restrict__ label_all,
      const float* __restrict__ fcw,
      float* __restrict__ out, int out_size) {
    __shared__ float As[2][TK][TNn + 4];     // As[k][n] = w'[k]*micro[n,k]
    __shared__ float Bs[2][TK][TMm + 4];     // Bs[k][m] = micro_all[m,k]
    __shared__ float sw[C_];                 // w'
    __shared__ float sAqP[TMm * 4];          // Aq partials [m_local*4 + kgrp]
    __shared__ float swgt[ROWS_PB][KTOP];
    __shared__ int   sgix[ROWS_PB][KTOP];

    const int tid = threadIdx.x;
    const int bx  = blockIdx.x;
    const int m0  = (bx & (MTILES - 1)) * TMm;
    const int n0  = (bx >> 4) * TNn;         // MTILES == 16

    sw[tid] = fcw[tid] - (1.0f / (float)C_);
    __syncthreads();

    const int lr  = tid >> 2;            // 0..63 loader row slot
    const int lkp = (tid & 3) << 2;      // k sub-offset 0,4,8,12
    const int tx  = tid & 15;            // m frag group: cols tx*8..+7
    const int ty  = tid >> 4;            // n frag group: rows ty*4..+3 (0..15)

    float4 pb[2], pa;
    float  aqp[2] = {0.f, 0.f};
    ull    acc[4][4];
    #pragma unroll
    for (int i = 0; i < 4; i++)
        #pragma unroll
        for (int j = 0; j < 4; j++) acc[i][j] = 0ull;

    auto LOAD = [&](int k0) {
        #pragma unroll
        for (int i = 0; i < 2; i++)
            pb[i] = *(const float4*)&micro_all[(m0 + lr + 64 * i) * C_ + k0 + lkp];
        pa = *(const float4*)&micro[(n0 + lr) * C_ + k0 + lkp];
    };
    auto STORE = [&](int buf, int k0) {
        float4 w4 = *(const float4*)&sw[k0 + lkp];
        #pragma unroll
        for (int i = 0; i < 2; i++) {
            int r = lr + 64 * i;
            Bs[buf][lkp + 0][r] = pb[i].x;
            Bs[buf][lkp + 1][r] = pb[i].y;
            Bs[buf][lkp + 2][r] = pb[i].z;
            Bs[buf][lkp + 3][r] = pb[i].w;
            aqp[i] += w4.x * pb[i].x * pb[i].x + w4.y * pb[i].y * pb[i].y
                    + w4.z * pb[i].z * pb[i].z + w4.w * pb[i].w * pb[i].w;
        }
        As[buf][lkp + 0][lr] = w4.x * pa.x;
        As[buf][lkp + 1][lr] = w4.y * pa.y;
        As[buf][lkp + 2][lr] = w4.z * pa.z;
        As[buf][lkp + 3][lr] = w4.w * pa.w;
    };

    LOAD(0);
    STORE(0, 0);
    __syncthreads();

    #pragma unroll 1
    for (int c = 0; c < C_ / TK; c++) {
        if (c < C_ / TK - 1) LOAD((c + 1) * TK);
        const int buf = c & 1;
        #pragma unroll
        for (int k = 0; k < TK; k++) {
            float4 a = *(const float4*)&As[buf][k][ty * 4];
            ulonglong2 b0 = *(const ulonglong2*)&Bs[buf][k][tx * 8];
            ulonglong2 b1 = *(const ulonglong2*)&Bs[buf][k][tx * 8 + 4];
            ull bb0 = b0.x, bb1 = b0.y, bb2 = b1.x, bb3 = b1.y;
            float av[4] = {a.x, a.y, a.z, a.w};
            #pragma unroll
            for (int i = 0; i < 4; i++) {
                ull aa = pack2(av[i]);
                fma2(acc[i][0], aa, bb0);
                fma2(acc[i][1], aa, bb1);
                fma2(acc[i][2], aa, bb2);
                fma2(acc[i][3], aa, bb3);
            }
        }
        if (c < C_ / TK - 1) {
            STORE((c + 1) & 1, (c + 1) * TK);
            __syncthreads();
        }
    }

    // Aq partials: slot (m_local*4 + kgrp) == tid + 256*i by construction
    sAqP[tid]       = aqp[0];
    sAqP[tid + 256] = aqp[1];
    __syncthreads();

    float aqv[8];
    #pragma unroll
    for (int t = 0; t < 8; t++) {
        float4 q = *(const float4*)&sAqP[(tx * 8 + t) * 4];
        aqv[t] = (q.x + q.y) + (q.z + q.w);
    }

    // ---- candidate epilogue: per-row top-6 of this 128-col tile ----
    // Row n owned by the 16 lanes sharing ty (tx = lane&15): shfl s=1..8.
    #pragma unroll
    for (int i = 0; i < 4; i++) {
        const int n = n0 + ty * 4 + i;
        ull key[8];
        #pragma unroll
        for (int jj = 0; jj < 4; jj++) {
            float lo, hi;
            unpack2(acc[i][jj], lo, hi);
            float v0 = aqv[2 * jj]     - 2.f * lo;
            float v1 = aqv[2 * jj + 1] - 2.f * hi;
            int c0 = m0 + tx * 8 + 2 * jj;
            key[2 * jj]     = ((ull)ordf(v0) << 32) | (u32)(~c0);
            key[2 * jj + 1] = ((ull)ordf(v1) << 32) | (u32)(~(c0 + 1));
        }
        #pragma unroll
        for (int it = 0; it < KTOP; it++) {
            ull m01 = key[0] > key[1] ? key[0] : key[1];
            ull m23 = key[2] > key[3] ? key[2] : key[3];
            ull m45 = key[4] > key[5] ? key[4] : key[5];
            ull m67 = key[6] > key[7] ? key[6] : key[7];
            ull m03 = m01 > m23 ? m01 : m23;
            ull m47 = m45 > m67 ? m45 : m67;
            ull kb  = m03 > m47 ? m03 : m47;
            #pragma unroll
            for (int s = 1; s < 16; s <<= 1) {
                ull o = __shfl_xor_sync(0xffffffffu, kb, s);
                if (o > kb) kb = o;
            }
            if (tx == 0)
                g_cand[n][(bx & (MTILES - 1)) * KTOP + it] = kb;
            int rel = (int)(~(u32)kb) - (m0 + tx * 8);
            #pragma unroll
            for (int e = 0; e < 8; e++)
                if (e == rel) key[e] = 0ull;
        }
    }

    // ---- software grid barrier (all 128 blocks co-resident) ----
    __syncthreads();
    __threadfence();
    if (tid == 0) {
        if (atomicAdd(&g_bar1, 1) == NBLK - 1) {
            g_flag = 1;                 // release
            __threadfence();
        }
        while (g_flag == 0) { }         // volatile spin
    }
    __syncthreads();
    __threadfence();                    // acquire: see all g_cand writes

    // ---- phase 2: rows [bx*4, bx*4+4) ----
    const int lane = tid & 31;
    const int w    = tid >> 5;          // 0..7
    if (w < ROWS_PB) {
        const int n = bx * ROWS_PB + w;
        const ull* cp = &g_cand[n][0];
        ull c0 = cp[lane], c1 = cp[lane + 32], c2 = cp[lane + 64];
        float fv[KTOP]; int fi[KTOP];
        #pragma unroll
        for (int it = 0; it < KTOP; it++) {
            ull b01 = c0 > c1 ? c0 : c1;
            ull kb  = b01 > c2 ? b01 : c2;
            #pragma unroll
            for (int s = 16; s; s >>= 1) {
                ull o = __shfl_xor_sync(0xffffffffu, kb, s);
                if (o > kb) kb = o;
            }
            fv[it] = deordf((u32)(kb >> 32));
            fi[it] = (int)(~(u32)kb) & 0x7fffffff;
            if (c0 == kb) c0 = 0ull;
            if (c1 == kb) c1 = 0ull;
            if (c2 == kb) c2 = 0ull;
        }
        if (lane == 0) {
            float e[KTOP], s = 0.f;
            #pragma unroll
            for (int k = 0; k < KTOP; k++) { e[k] = expf(fv[k] - fv[0]); s += e[k]; }
            float inv = 1.f / s;
            float lab = label[n];
            float co = 0.f;
            #pragma unroll
            for (int k = 0; k < KTOP; k++) {
                float ck = e[k] * inv;
                swgt[w][k] = ck; sgix[w][k] = fi[k];
                co += ck * fabsf(label_all[fi[k]] - lab);
            }
            g_rowco[n] = co;
        }
    }
    __syncthreads();

    // outputs: 4 rows x 256 cols (col = tid)
    #pragma unroll
    for (int r = 0; r < ROWS_PB; r++) {
        const int n = bx * ROWS_PB + r;
        float o = micro[n * C_ + tid];
        #pragma unroll
        for (int k = 0; k < KTOP; k++)
            o += swgt[r][k] * micro_all[sgix[r][k] * C_ + tid];
        out[n * C_ + tid] = o;
    }

    // deterministic co_loss: last arriving block does a fixed-order tree,
    // then resets barrier state for graph replays.
    __threadfence();
    __syncthreads();
    __shared__ int isLast;
    if (tid == 0)
        isLast = (atomicAdd(&g_bar2, 1) == NBLK - 1);
    __syncthreads();
    if (isLast) {
        __shared__ float red[256];
        red[tid] = g_rowco[tid] + g_rowco[tid + 256];
        __syncthreads();
        #pragma unroll
        for (int s2 = 128; s2 > 0; s2 >>= 1) {
            if (tid < s2) red[tid] += red[tid + s2];
            __syncthreads();
        }
        if (tid == 0) {
            if (out_size > N_ * C_)
                out[N_ * C_] = 1e-4f + red[0] / (float)N_;
            g_bar1 = 0; g_bar2 = 0; g_flag = 0;   // reset for replay
        }
    }
}

// ---------------------------------------------------------------------------
extern "C" void kernel_launch(void* const* d_in, const int* in_sizes, int n_in,
                              void* d_out, int out_size) {
    const float* micro     = (const float*)d_in[0];   // [512, 256]
    const float* label     = (const float*)d_in[1];   // [512]
    const float* micro_all = (const float*)d_in[2];   // [2048, 256]
    const float* label_all = (const float*)d_in[3];   // [2048]
    const float* fc_w      = (const float*)d_in[4];   // [256]
    float* out = (float*)d_out;

    fused<<<NBLK, 256>>>(micro, micro_all, label, label_all, fc_w,
                         out, out_size);
}

// round 14
// speedup vs baseline: 1.2604x; 1.2604x over previous
#include <cuda_runtime.h>
#include <math.h>

#define N_   512
#define M_   2048
#define C_   256
#define KTOP 6

typedef unsigned long long ull;
typedef unsigned int u32;

// Scratch (static __device__ globals: allocation-free per harness rules)
__device__ float g_anti[2][N_ * M_];   // split-K partials
__device__ float g_rowco[N_];
__device__ int   g_cnt = 0;

// ---- packed f32x2 helpers (FFMA2: 2 FMA per instruction on sm_103a) -------
__device__ __forceinline__ ull pack2(float x) {
    ull r; asm("mov.b64 %0, {%1, %1};" : "=l"(r) : "f"(x)); return r;
}
__device__ __forceinline__ void fma2(ull& d, ull a, ull b) {
    asm("fma.rn.f32x2 %0, %1, %2, %0;" : "+l"(d) : "l"(a), "l"(b));
}
__device__ __forceinline__ void unpack2(ull v, float& lo, float& hi) {
    asm("mov.b64 {%0, %1}, %2;" : "=f"(lo), "=f"(hi) : "l"(v));
}
// ---- order-preserving float <-> u32 (monotone under unsigned compare) -----
__device__ __forceinline__ u32 ordf(float v) {
    u32 s = __float_as_uint(v);
    return s ^ (u32)(((int)s >> 31) | 0x80000000);
}
__device__ __forceinline__ float deordf(u32 o) {
    u32 s = (o & 0x80000000u) ? (o ^ 0x80000000u) : ~o;
    return __uint_as_float(s);
}

// ---------------------------------------------------------------------------
// Kernel 1 (UNCHANGED from R8 — measured 17.5us, ~85% of fp32 SIMT ceiling):
// partial_z[n,m] = Aq_z[m] - 2 * dot_z(w'*micro[n], micro_all[m])
//   w'[c] = fc_w[c] - 1/C ; Aq_z over this block's K-half.
//   (per-row Bq[n] dropped: row-constant -> invariant for top-k + exp weights)
// Tile 128(m) x 64(n) x Khalf(128), 128 threads, 8x8 frag, TK=16, double-buf.
// grid (16, 8, 2) = 256 blocks -> 2 CTAs/SM.
// ---------------------------------------------------------------------------
#define TMm 128
#define TNn 64
#define TK  16
#define KHALF 128

__global__ void __launch_bounds__(128, 2)
anti_gemm(const float* __restrict__ micro,
          const float* __restrict__ micro_all,
          const float* __restrict__ fc_w) {
    __shared__ float As[2][TK][TNn + 4];     // As[k][n] = w'[k]*micro[n,k]
    __shared__ float Bs[2][TK][TMm + 4];     // Bs[k][m] = micro_all[m,k]
    __shared__ float sw[C_];                 // w'
    __shared__ float sAqP[TMm * 4];          // Aq partials [m_local*4 + kgrp]

    const int tid = threadIdx.x;
    const int m0 = blockIdx.x * TMm;
    const int n0 = blockIdx.y * TNn;
    const int z  = blockIdx.z;
    const int kb = z * KHALF;

    sw[tid]       = fc_w[tid]       - (1.0f / (float)C_);
    sw[tid + 128] = fc_w[tid + 128] - (1.0f / (float)C_);
    __syncthreads();

    const int lr  = tid >> 2;           // 0..31 loader row slot
    const int lkp = (tid & 3) << 2;     // k sub-offset 0,4,8,12
    const int tx  = tid & 15;           // m frag group (8 cols)
    const int ty  = tid >> 4;           // n frag group (8 rows), 0..7

    float4 pb[4], pa[2];
    float  aqp[4] = {0.f, 0.f, 0.f, 0.f};
    ull    acc[8][4];
    #pragma unroll
    for (int i = 0; i < 8; i++)
        #pragma unroll
        for (int j = 0; j < 4; j++) acc[i][j] = 0ull;

    auto LOAD = [&](int k0) {           // k0 global
        #pragma unroll
        for (int i = 0; i < 4; i++)
            pb[i] = *(const float4*)&micro_all[(m0 + lr + 32 * i) * C_ + k0 + lkp];
        #pragma unroll
        for (int i = 0; i < 2; i++)
            pa[i] = *(const float4*)&micro[(n0 + lr + 32 * i) * C_ + k0 + lkp];
    };
    auto STORE = [&](int buf, int k0) {
        float4 w4 = *(const float4*)&sw[k0 + lkp];
        #pragma unroll
        for (int i = 0; i < 4; i++) {
            int r = lr + 32 * i;
            Bs[buf][lkp + 0][r] = pb[i].x;
            Bs[buf][lkp + 1][r] = pb[i].y;
            Bs[buf][lkp + 2][r] = pb[i].z;
            Bs[buf][lkp + 3][r] = pb[i].w;
            aqp[i] += w4.x * pb[i].x * pb[i].x + w4.y * pb[i].y * pb[i].y
                    + w4.z * pb[i].z * pb[i].z + w4.w * pb[i].w * pb[i].w;
        }
        #pragma unroll
        for (int i = 0; i < 2; i++) {
            int r = lr + 32 * i;
            As[buf][lkp + 0][r] = w4.x * pa[i].x;
            As[buf][lkp + 1][r] = w4.y * pa[i].y;
            As[buf][lkp + 2][r] = w4.z * pa[i].z;
            As[buf][lkp + 3][r] = w4.w * pa[i].w;
        }
    };

    LOAD(kb);
    STORE(0, kb);
    __syncthreads();

    #pragma unroll 1
    for (int c = 0; c < KHALF / TK; c++) {
        if (c < KHALF / TK - 1) LOAD(kb + (c + 1) * TK);
        const int buf = c & 1;
        #pragma unroll
        for (int k = 0; k < TK; k++) {
            float4 a0 = *(const float4*)&As[buf][k][ty * 8];
            float4 a1 = *(const float4*)&As[buf][k][ty * 8 + 4];
            ulonglong2 b0 = *(const ulonglong2*)&Bs[buf][k][tx * 8];
            ulonglong2 b1 = *(const ulonglong2*)&Bs[buf][k][tx * 8 + 4];
            ull bb0 = b0.x, bb1 = b0.y, bb2 = b1.x, bb3 = b1.y;
            float av[8] = {a0.x, a0.y, a0.z, a0.w, a1.x, a1.y, a1.z, a1.w};
            #pragma unroll
            for (int i = 0; i < 8; i++) {
                ull aa = pack2(av[i]);
                fma2(acc[i][0], aa, bb0);
                fma2(acc[i][1], aa, bb1);
                fma2(acc[i][2], aa, bb2);
                fma2(acc[i][3], aa, bb3);
            }
        }
        if (c < KHALF / TK - 1) {
            STORE((c + 1) & 1, kb + (c + 1) * TK);
            __syncthreads();
        }
    }

    // Aq partials: slot (m_local*4 + kgrp) == tid + 128*i by construction
    #pragma unroll
    for (int i = 0; i < 4; i++) sAqP[tid + 128 * i] = aqp[i];
    __syncthreads();

    float aqv[8];
    #pragma unroll
    for (int t = 0; t < 8; t++) {
        float4 q = *(const float4*)&sAqP[(tx * 8 + t) * 4];
        aqv[t] = (q.x + q.y) + (q.z + q.w);
    }

    float* base = &g_anti[z][0];
    #pragma unroll
    for (int i = 0; i < 8; i++) {
        int n = n0 + ty * 8 + i;
        float lo0, hi0, lo1, hi1;
        unpack2(acc[i][0], lo0, hi0);
        unpack2(acc[i][1], lo1, hi1);
        float4 o0 = make_float4(aqv[0] - 2.f * lo0, aqv[1] - 2.f * hi0,
                                aqv[2] - 2.f * lo1, aqv[3] - 2.f * hi1);
        unpack2(acc[i][2], lo0, hi0);
        unpack2(acc[i][3], lo1, hi1);
        float4 o1 = make_float4(aqv[4] - 2.f * lo0, aqv[5] - 2.f * hi0,
                                aqv[6] - 2.f * lo1, aqv[7] - 2.f * hi1);
        float* dst = &base[n * M_ + m0 + tx * 8];
        *(float4*)&dst[0] = o0;
        *(float4*)&dst[4] = o1;
    }
}

// ---------------------------------------------------------------------------
// Kernel 2: 128 blocks x 512 threads (1 CTA/SM, ONE wave). Each block owns
// 4 rows; 4 warps per row, each warp selects top-6 of its 512-col segment
// using u64 keys (ord(val)<<32 | ~col): unsigned max == (val desc, col asc)
// — exact lax.top_k order; one shfl per hop instead of two. First warp of
// each row-group merges the 24 candidates; exp weights over the 6 (full
// softmax denominator cancels); block writes the 4 output rows; last block
// does the deterministic co_loss tree.
// ---------------------------------------------------------------------------
__global__ void __launch_bounds__(512)
topk_kernel(const float* __restrict__ micro,
            const float* __restrict__ micro_all,
            const float* __restrict__ label,
            const float* __restrict__ label_all,
            float* __restrict__ out, int out_size) {
    const int tid  = threadIdx.x;
    const int lane = tid & 31;
    const int w    = tid >> 5;          // 0..15
    const int g    = w >> 2;            // row group 0..3
    const int seg  = w & 3;             // 512-col segment within row
    const int n    = blockIdx.x * 4 + g;
    const int base = seg * 512 + lane * 16;  // 16 contiguous cols per lane

    __shared__ ull   scand[16][KTOP];   // per-warp top-6 keys
    __shared__ float swgt[4][KTOP];
    __shared__ int   sgix[4][KTOP];
    __shared__ float srowco[4];

    // load + sum split-K partials, build keys
    const float* r0 = &g_anti[0][n * M_];
    const float* r1 = &g_anti[1][n * M_];
    ull key[16];
    #pragma unroll
    for (int q = 0; q < 4; q++) {
        float4 p = *(const float4*)&r0[base + q * 4];
        float4 s = *(const float4*)&r1[base + q * 4];
        float v0 = p.x + s.x, v1 = p.y + s.y, v2 = p.z + s.z, v3 = p.w + s.w;
        int c0 = base + q * 4;
        key[q * 4 + 0] = ((ull)ordf(v0) << 32) | (u32)(~c0);
        key[q * 4 + 1] = ((ull)ordf(v1) << 32) | (u32)(~(c0 + 1));
        key[q * 4 + 2] = ((ull)ordf(v2) << 32) | (u32)(~(c0 + 2));
        key[q * 4 + 3] = ((ull)ordf(v3) << 32) | (u32)(~(c0 + 3));
    }

    #pragma unroll
    for (int it = 0; it < KTOP; it++) {
        // branchless tree max over 16 keys (depth 4)
        ull t0 = key[0]  > key[1]  ? key[0]  : key[1];
        ull t1 = key[2]  > key[3]  ? key[2]  : key[3];
        ull t2 = key[4]  > key[5]  ? key[4]  : key[5];
        ull t3 = key[6]  > key[7]  ? key[6]  : key[7];
        ull t4 = key[8]  > key[9]  ? key[8]  : key[9];
        ull t5 = key[10] > key[11] ? key[10] : key[11];
        ull t6 = key[12] > key[13] ? key[12] : key[13];
        ull t7 = key[14] > key[15] ? key[14] : key[15];
        ull u0 = t0 > t1 ? t0 : t1;
        ull u1 = t2 > t3 ? t2 : t3;
        ull u2 = t4 > t5 ? t4 : t5;
        ull u3 = t6 > t7 ? t6 : t7;
        ull x0 = u0 > u1 ? u0 : u1;
        ull x1 = u2 > u3 ? u2 : u3;
        ull kb = x0 > x1 ? x0 : x1;
        #pragma unroll
        for (int s = 16; s; s >>= 1) {
            ull o = __shfl_xor_sync(0xffffffffu, kb, s);
            if (o > kb) kb = o;
        }
        if (lane == 0) scand[w][it] = kb;
        // owner removes the winner (keys unique via ~col)
        int rel = (int)(~(u32)kb) - base;   // 0..15 only for owning lane
        #pragma unroll
        for (int e = 0; e < 16; e++)
            if (e == rel) key[e] = 0ull;
    }
    __syncthreads();

    // merge 24 candidates per row (first warp of each group)
    if (seg == 0) {
        ull ck = (lane < 4 * KTOP) ? scand[g * 4 + lane / KTOP][lane % KTOP] : 0ull;
        float fv[KTOP]; int fi[KTOP];
        #pragma unroll
        for (int it = 0; it < KTOP; it++) {
            ull kb = ck;
            #pragma unroll
            for (int s = 16; s; s >>= 1) {
                ull o = __shfl_xor_sync(0xffffffffu, kb, s);
                if (o > kb) kb = o;
            }
            fv[it] = deordf((u32)(kb >> 32));
            fi[it] = (int)(~(u32)kb) & 0x7fffffff;
            if (ck == kb) ck = 0ull;        // unique keys: one owner
        }
        if (lane == 0) {
            float e[KTOP], s = 0.f;
            #pragma unroll
            for (int k = 0; k < KTOP; k++) { e[k] = expf(fv[k] - fv[0]); s += e[k]; }
            float inv = 1.f / s;
            float lab = label[n];
            float co = 0.f;
            #pragma unroll
            for (int k = 0; k < KTOP; k++) {
                float ck2 = e[k] * inv;
                swgt[g][k] = ck2; sgix[g][k] = fi[k];
                co += ck2 * fabsf(label_all[fi[k]] - lab);
            }
            srowco[g] = co;
        }
    }
    __syncthreads();

    // outputs: 4 rows x 256 cols with 512 threads -> 2 cols per thread
    {
        const int r  = tid >> 7;          // 0..3
        const int c0 = tid & 127;
        const int nn = blockIdx.x * 4 + r;
        float o0 = micro[nn * C_ + c0];
        float o1 = micro[nn * C_ + c0 + 128];
        #pragma unroll
        for (int k = 0; k < KTOP; k++) {
            const float* row = &micro_all[sgix[r][k] * C_];
            float wk = swgt[r][k];
            o0 += wk * row[c0];
            o1 += wk * row[c0 + 128];
        }
        out[nn * C_ + c0]       = o0;
        out[nn * C_ + c0 + 128] = o1;
    }
    if (tid < 4) g_rowco[blockIdx.x * 4 + tid] = srowco[tid];

    // deterministic co_loss: last arriving block does a fixed-order tree
    __threadfence();
    __syncthreads();
    __shared__ int isLast;
    if (tid == 0)
        isLast = (atomicAdd(&g_cnt, 1) == (int)gridDim.x - 1);
    __syncthreads();
    if (isLast) {
        __shared__ float red[256];
        if (tid < 256) red[tid] = g_rowco[tid] + g_rowco[tid + 256];
        __syncthreads();
        #pragma unroll
        for (int s2 = 128; s2 > 0; s2 >>= 1) {
            if (tid < s2) red[tid] += red[tid + s2];
            __syncthreads();
        }
        if (tid == 0) {
            if (out_size > N_ * C_)
                out[N_ * C_] = 1e-4f + red[0] / (float)N_;
            g_cnt = 0;   // reset for graph replays
        }
    }
}

// ---------------------------------------------------------------------------
extern "C" void kernel_launch(void* const* d_in, const int* in_sizes, int n_in,
                              void* d_out, int out_size) {
    const float* micro     = (const float*)d_in[0];   // [512, 256]
    const float* label     = (const float*)d_in[1];   // [512]
    const float* micro_all = (const float*)d_in[2];   // [2048, 256]
    const float* label_all = (const float*)d_in[3];   // [2048]
    const float* fc_w      = (const float*)d_in[4];   // [256]
    float* out = (float*)d_out;

    anti_gemm<<<dim3(M_ / TMm, N_ / TNn, 2), 128>>>(micro, micro_all, fc_w);
    topk_kernel<<<N_ / 4, 512>>>(micro, micro_all, label, label_all, out, out_size);
}

// round 17
// speedup vs baseline: 1.2695x; 1.0072x over previous
#include <cuda_runtime.h>
#include <math.h>

#define N_   512
#define M_   2048
#define C_   256
#define KTOP 6

#define TMm 128
#define TNn 64
#define TK  16
#define KHALF 128
#define NBLK 256                     // (16 mtiles) x (8 ntiles) x (2 ksplit)

typedef unsigned long long ull;
typedef unsigned int u32;

// Scratch (static __device__ globals: allocation-free per harness rules)
__device__ float g_anti[2][N_ * M_];   // split-K partials
__device__ float g_rowco[N_];
__device__ int   g_bar1 = 0, g_bar2 = 0;
__device__ volatile int g_flag = 0;

// ---- packed f32x2 helpers (FFMA2: 2 FMA per instruction on sm_103a) -------
__device__ __forceinline__ ull pack2(float x) {
    ull r; asm("mov.b64 %0, {%1, %1};" : "=l"(r) : "f"(x)); return r;
}
__device__ __forceinline__ void fma2(ull& d, ull a, ull b) {
    asm("fma.rn.f32x2 %0, %1, %2, %0;" : "+l"(d) : "l"(a), "l"(b));
}
__device__ __forceinline__ void unpack2(ull v, float& lo, float& hi) {
    asm("mov.b64 {%0, %1}, %2;" : "=f"(lo), "=f"(hi) : "l"(v));
}
// ---- order-preserving float <-> u32 (monotone under unsigned compare) -----
__device__ __forceinline__ u32 ordf(float v) {
    u32 s = __float_as_uint(v);
    return s ^ (u32)(((int)s >> 31) | 0x80000000);
}
__device__ __forceinline__ float deordf(u32 o) {
    u32 s = (o & 0x80000000u) ? (o ^ 0x80000000u) : ~o;
    return __uint_as_float(s);
}

// ---------------------------------------------------------------------------
// ONE fused kernel, 256 blocks x 128 threads, 2 CTAs/SM (256 <= 296 blocks
// co-resident -> software grid barrier is deadlock-free).
//
// Phase 1 — BYTE-IDENTICAL to the measured-17.5us R8 GEMM mainloop:
//   partial_z[n,m] = Aq_z[m] - 2*dot_z(w'*micro[n], micro_all[m]),
//   w' = fc_w - 1/C (folds dis.mean); per-row Bq[n] dropped (row-constant ->
//   invariant for top-k selection and exp(anti - rowmax) weights).
//   Tile 128m x 64n x 128k, 8x8 frags in packed-f32x2 accumulators.
//
// Grid barrier, then Phase 2 — each block owns 2 rows:
//   2 warps per row, each selects top-6 of its 1024 cols via u64 keys
//   (ord(val)<<32 | ~col): unsigned max == (val desc, col asc) — exact
//   lax.top_k order independent of scan order. 12-candidate merge per row,
//   exp weights over the 6 (full softmax denominator cancels analytically),
//   output rows, per-row co; deterministic last-block co_loss tree; barrier
//   state reset for graph replays. Phase-2 anti reads hit hot L2.
// ---------------------------------------------------------------------------
__global__ void __launch_bounds__(128, 2)
fused(const float* __restrict__ micro,
      const float* __restrict__ micro_all,
      const float* __restrict__ label,
      const float* __restrict__ label_all,
      const float* __restrict__ fcw,
      float* __restrict__ out, int out_size) {
    __shared__ float As[2][TK][TNn + 4];     // As[k][n] = w'[k]*micro[n,k]
    __shared__ float Bs[2][TK][TMm + 4];     // Bs[k][m] = micro_all[m,k]
    __shared__ float sw[C_];                 // w'
    __shared__ float sAqP[TMm * 4];          // Aq partials [m_local*4 + kgrp]
    __shared__ ull   scand[4][KTOP];         // phase-2 per-warp candidates
    __shared__ float swgt[2][KTOP];
    __shared__ int   sgix[2][KTOP];
    __shared__ float srowco[2];

    const int tid = threadIdx.x;
    const int bx  = blockIdx.x;
    // R8 grid (16, 8, 2) flattened:
    const int m0 = (bx & 15) * TMm;
    const int n0 = ((bx >> 4) & 7) * TNn;
    const int z  = bx >> 7;
    const int kb = z * KHALF;

    sw[tid]       = fcw[tid]       - (1.0f / (float)C_);
    sw[tid + 128] = fcw[tid + 128] - (1.0f / (float)C_);
    __syncthreads();

    const int lr  = tid >> 2;           // 0..31 loader row slot
    const int lkp = (tid & 3) << 2;     // k sub-offset 0,4,8,12
    const int tx  = tid & 15;           // m frag group (8 cols)
    const int ty  = tid >> 4;           // n frag group (8 rows), 0..7

    {
        float4 pb[4], pa[2];
        float  aqp[4] = {0.f, 0.f, 0.f, 0.f};
        ull    acc[8][4];
        #pragma unroll
        for (int i = 0; i < 8; i++)
            #pragma unroll
            for (int j = 0; j < 4; j++) acc[i][j] = 0ull;

        auto LOAD = [&](int k0) {
            #pragma unroll
            for (int i = 0; i < 4; i++)
                pb[i] = *(const float4*)&micro_all[(m0 + lr + 32 * i) * C_ + k0 + lkp];
            #pragma unroll
            for (int i = 0; i < 2; i++)
                pa[i] = *(const float4*)&micro[(n0 + lr + 32 * i) * C_ + k0 + lkp];
        };
        auto STORE = [&](int buf, int k0) {
            float4 w4 = *(const float4*)&sw[k0 + lkp];
            #pragma unroll
            for (int i = 0; i < 4; i++) {
                int r = lr + 32 * i;
                Bs[buf][lkp + 0][r] = pb[i].x;
                Bs[buf][lkp + 1][r] = pb[i].y;
                Bs[buf][lkp + 2][r] = pb[i].z;
                Bs[buf][lkp + 3][r] = pb[i].w;
                aqp[i] += w4.x * pb[i].x * pb[i].x + w4.y * pb[i].y * pb[i].y
                        + w4.z * pb[i].z * pb[i].z + w4.w * pb[i].w * pb[i].w;
            }
            #pragma unroll
            for (int i = 0; i < 2; i++) {
                int r = lr + 32 * i;
                As[buf][lkp + 0][r] = w4.x * pa[i].x;
                As[buf][lkp + 1][r] = w4.y * pa[i].y;
                As[buf][lkp + 2][r] = w4.z * pa[i].z;
                As[buf][lkp + 3][r] = w4.w * pa[i].w;
            }
        };

        LOAD(kb);
        STORE(0, kb);
        __syncthreads();

        #pragma unroll 1
        for (int c = 0; c < KHALF / TK; c++) {
            if (c < KHALF / TK - 1) LOAD(kb + (c + 1) * TK);
            const int buf = c & 1;
            #pragma unroll
            for (int k = 0; k < TK; k++) {
                float4 a0 = *(const float4*)&As[buf][k][ty * 8];
                float4 a1 = *(const float4*)&As[buf][k][ty * 8 + 4];
                ulonglong2 b0 = *(const ulonglong2*)&Bs[buf][k][tx * 8];
                ulonglong2 b1 = *(const ulonglong2*)&Bs[buf][k][tx * 8 + 4];
                ull bb0 = b0.x, bb1 = b0.y, bb2 = b1.x, bb3 = b1.y;
                float av[8] = {a0.x, a0.y, a0.z, a0.w, a1.x, a1.y, a1.z, a1.w};
                #pragma unroll
                for (int i = 0; i < 8; i++) {
                    ull aa = pack2(av[i]);
                    fma2(acc[i][0], aa, bb0);
                    fma2(acc[i][1], aa, bb1);
                    fma2(acc[i][2], aa, bb2);
                    fma2(acc[i][3], aa, bb3);
                }
            }
            if (c < KHALF / TK - 1) {
                STORE((c + 1) & 1, kb + (c + 1) * TK);
                __syncthreads();
            }
        }

        // Aq partials: slot (m_local*4 + kgrp) == tid + 128*i by construction
        #pragma unroll
        for (int i = 0; i < 4; i++) sAqP[tid + 128 * i] = aqp[i];
        __syncthreads();

        float aqv[8];
        #pragma unroll
        for (int t = 0; t < 8; t++) {
            float4 q = *(const float4*)&sAqP[(tx * 8 + t) * 4];
            aqv[t] = (q.x + q.y) + (q.z + q.w);
        }

        float* base = &g_anti[z][0];
        #pragma unroll
        for (int i = 0; i < 8; i++) {
            int n = n0 + ty * 8 + i;
            float lo0, hi0, lo1, hi1;
            unpack2(acc[i][0], lo0, hi0);
            unpack2(acc[i][1], lo1, hi1);
            float4 o0 = make_float4(aqv[0] - 2.f * lo0, aqv[1] - 2.f * hi0,
                                    aqv[2] - 2.f * lo1, aqv[3] - 2.f * hi1);
            unpack2(acc[i][2], lo0, hi0);
            unpack2(acc[i][3], lo1, hi1);
            float4 o1 = make_float4(aqv[4] - 2.f * lo0, aqv[5] - 2.f * hi0,
                                    aqv[6] - 2.f * lo1, aqv[7] - 2.f * hi1);
            float* dst = &base[n * M_ + m0 + tx * 8];
            *(float4*)&dst[0] = o0;
            *(float4*)&dst[4] = o1;
        }
    }

    // ---- software grid barrier (all 256 blocks co-resident at 2 CTAs/SM) --
    __syncthreads();
    __threadfence();
    if (tid == 0) {
        if (atomicAdd(&g_bar1, 1) == NBLK - 1) {
            g_flag = 1;                 // release
            __threadfence();
        }
        while (g_flag == 0) { }         // volatile spin
    }
    __syncthreads();
    __threadfence();                    // acquire: all g_anti writes visible

    // ---- phase 2: rows {bx*2, bx*2+1}; 2 warps per row, 1024 cols each ----
    {
        const int lane = tid & 31;
        const int w    = tid >> 5;      // 0..3
        const int row  = w >> 1;        // 0..1
        const int h    = w & 1;         // column half
        const int n    = bx * 2 + row;
        const float* r0 = &g_anti[0][n * M_ + h * 1024];
        const float* r1 = &g_anti[1][n * M_ + h * 1024];

        // 32 keys/lane: col = h*1024 + j*128 + lane*4 + e (coalesced float4)
        ull key[32];
        #pragma unroll
        for (int j = 0; j < 8; j++) {
            float4 p = *(const float4*)&r0[j * 128 + lane * 4];
            float4 q = *(const float4*)&r1[j * 128 + lane * 4];
            int c0 = h * 1024 + j * 128 + lane * 4;
            key[j * 4 + 0] = ((ull)ordf(p.x + q.x) << 32) | (u32)(~c0);
            key[j * 4 + 1] = ((ull)ordf(p.y + q.y) << 32) | (u32)(~(c0 + 1));
            key[j * 4 + 2] = ((ull)ordf(p.z + q.z) << 32) | (u32)(~(c0 + 2));
            key[j * 4 + 3] = ((ull)ordf(p.w + q.w) << 32) | (u32)(~(c0 + 3));
        }

        #pragma unroll
        for (int it = 0; it < KTOP; it++) {
            // branchless tree max over 32 keys
            ull t[16];
            #pragma unroll
            for (int e = 0; e < 16; e++)
                t[e] = key[2 * e] > key[2 * e + 1] ? key[2 * e] : key[2 * e + 1];
            #pragma unroll
            for (int e = 0; e < 8; e++)
                t[e] = t[2 * e] > t[2 * e + 1] ? t[2 * e] : t[2 * e + 1];
            #pragma unroll
            for (int e = 0; e < 4; e++)
                t[e] = t[2 * e] > t[2 * e + 1] ? t[2 * e] : t[2 * e + 1];
            ull kb0 = t[0] > t[1] ? t[0] : t[1];
            ull kb1 = t[2] > t[3] ? t[2] : t[3];
            ull kb  = kb0 > kb1 ? kb0 : kb1;
            #pragma unroll
            for (int s = 16; s; s >>= 1) {
                ull o = __shfl_xor_sync(0xffffffffu, kb, s);
                if (o > kb) kb = o;
            }
            if (lane == 0) scand[w][it] = kb;
            // removal by equality (keys globally unique via ~col)
            #pragma unroll
            for (int e = 0; e < 32; e++)
                if (key[e] == kb) key[e] = 0ull;
        }
    }
    __syncthreads();

    // merge 12 candidates per row (warps 0 and 1 handle rows 0 and 1)
    {
        const int lane = tid & 31;
        const int w    = tid >> 5;
        if (w < 2) {
            const int n = bx * 2 + w;
            ull ck = (lane < 2 * KTOP) ? scand[w * 2 + lane / KTOP][lane % KTOP]
                                       : 0ull;
            float fv[KTOP]; int fi[KTOP];
            #pragma unroll
            for (int it = 0; it < KTOP; it++) {
                ull kb = ck;
                #pragma unroll
                for (int s = 16; s; s >>= 1) {
                    ull o = __shfl_xor_sync(0xffffffffu, kb, s);
                    if (o > kb) kb = o;
                }
                fv[it] = deordf((u32)(kb >> 32));
                fi[it] = (int)(~(u32)kb) & 0x7fffffff;
                if (ck == kb) ck = 0ull;    // unique keys: one owner
            }
            if (lane == 0) {
                float e[KTOP], s = 0.f;
                #pragma unroll
                for (int k = 0; k < KTOP; k++) { e[k] = expf(fv[k] - fv[0]); s += e[k]; }
                float inv = 1.f / s;
                float lab = label[n];
                float co = 0.f;
                #pragma unroll
                for (int k = 0; k < KTOP; k++) {
                    float ck2 = e[k] * inv;
                    swgt[w][k] = ck2; sgix[w][k] = fi[k];
                    co += ck2 * fabsf(label_all[fi[k]] - lab);
                }
                srowco[w] = co;
            }
        }
    }
    __syncthreads();

    // outputs: 2 rows x 256 cols with 128 threads (4 stores/thread)
    #pragma unroll
    for (int r = 0; r < 2; r++) {
        const int n = bx * 2 + r;
        #pragma unroll
        for (int hh = 0; hh < 2; hh++) {
            int c = tid + hh * 128;
            float o = micro[n * C_ + c];
            #pragma unroll
            for (int k = 0; k < KTOP; k++)
                o += swgt[r][k] * micro_all[sgix[r][k] * C_ + c];
            out[n * C_ + c] = o;
        }
    }
    if (tid < 2) g_rowco[bx * 2 + tid] = srowco[tid];

    // deterministic co_loss: last arriving block does a fixed-order tree,
    // then resets barrier state for graph replays.
    __threadfence();
    __syncthreads();
    __shared__ int isLast;
    if (tid == 0)
        isLast = (atomicAdd(&g_bar2, 1) == NBLK - 1);
    __syncthreads();
    if (isLast) {
        __shared__ float red[128];
        red[tid] = (g_rowco[tid] + g_rowco[tid + 128])
                 + (g_rowco[tid + 256] + g_rowco[tid + 384]);
        __syncthreads();
        #pragma unroll
        for (int s2 = 64; s2 > 0; s2 >>= 1) {
            if (tid < s2) red[tid] += red[tid + s2];
            __syncthreads();
        }
        if (tid == 0) {
            if (out_size > N_ * C_)
                out[N_ * C_] = 1e-4f + red[0] / (float)N_;
            g_bar1 = 0; g_bar2 = 0; g_flag = 0;   // reset for replay
        }
    }
}

// ---------------------------------------------------------------------------
extern "C" void kernel_launch(void* const* d_in, const int* in_sizes, int n_in,
                              void* d_out, int out_size) {
    const float* micro     = (const float*)d_in[0];   // [512, 256]
    const float* label     = (const float*)d_in[1];   // [512]
    const float* micro_all = (const float*)d_in[2];   // [2048, 256]
    const float* label_all = (const float*)d_in[3];   // [2048]
    const float* fc_w      = (const float*)d_in[4];   // [256]
    float* out = (float*)d_out;

    fused<<<NBLK, 128>>>(micro, micro_all, label, label_all, fc_w,
                         out, out_size);
}